// round 15
// baseline (speedup 1.0000x reference)
#include <cuda_runtime.h>

#define BDIM 4
#define TDIM 300
#define NDIM 200
#define NIN  100
#define KDIM 10

#define BTN (BDIM*TDIM*NDIM)     // 240000
#define OUT_TOTAL (NIN*NDIM + NDIM*NDIM + NDIM*KDIM)  // 62000

#define D1  0.8f
#define D2  0.64f
#define D4  0.4096f
#define D8  0.16777216f
#define D16 0.0281474976710656f
#define D32 0.000792281625142643f

// scratch (device globals — no cudaMalloc allowed)
__device__ __align__(16) float g_Yr[BTN];                  // revfilter(G2)
__device__ __align__(16) float g_e1f[BDIM * TDIM * KDIM];  // revfilter(e1)

typedef unsigned long long ull;

__device__ __forceinline__ float dpow_lane(int l) {
    float p = 1.f;
    if (l & 1)  p *= D1;
    if (l & 2)  p *= D2;
    if (l & 4)  p *= D4;
    if (l & 8)  p *= D8;
    if (l & 16) p *= D16;
    return p;
}

__device__ __forceinline__ float warp_rscan(float a, int lane) {
    float tmp;
    tmp = __shfl_down_sync(0xffffffffu, a, 1);  if (lane < 31) a = fmaf(tmp, D1,  a);
    tmp = __shfl_down_sync(0xffffffffu, a, 2);  if (lane < 30) a = fmaf(tmp, D2,  a);
    tmp = __shfl_down_sync(0xffffffffu, a, 4);  if (lane < 28) a = fmaf(tmp, D4,  a);
    tmp = __shfl_down_sync(0xffffffffu, a, 8);  if (lane < 24) a = fmaf(tmp, D8,  a);
    tmp = __shfl_down_sync(0xffffffffu, a, 16); if (lane < 16) a = fmaf(tmp, D16, a);
    return a;
}

// ---------------------------------------------------------------------------
// Kernel 1: G2 + reverse filter -> Yr (split-T, 2 warps per neuron); e1f in
// dedicated blocks. (R14-proven; zero-out blocks removed — k_sparse covers
// every output element with plain stores.)
//  blocks  0..99  : (b, 8-neuron tile), 16 warps = 8 neurons x 2 T-halves.
//  blocks 100..103: e1f = revfilter(e1) for batch b = bx-100.
// ---------------------------------------------------------------------------
__global__ void __launch_bounds__(512) k_g2(
        const float* __restrict__ v, const float* __restrict__ z,
        const float* __restrict__ e1, const float* __restrict__ e2,
        const float* __restrict__ w_out) {
    __shared__ float s_z[8][304];
    __shared__ float s_v[8][304];
    __shared__ float s_et[10][304];    // e1 transposed [k][t] (G2 blocks)
                                       // or flat e1 [t*10+k] (e1f blocks)
    __shared__ float s_c[2][8];        // cross-half carries: [0]=Lf160 [1]=Yr160

    const int tid  = threadIdx.x;
    const int lane = tid & 31;
    const int wrp  = tid >> 5;         // 0..15
    const int bx   = blockIdx.x;

    const float dl  = dpow_lane(lane);
    const float drl = D32 / dl;        // d^(32-lane)

    if (bx < 100) {
        const int b  = bx / 25;
        const int n0 = (bx % 25) * 8;          // 25*8 = 200 exact
        const int nrn  = wrp >> 1;             // 0..7
        const int half = wrp & 1;              // 0 = t<160, 1 = t>=160
        const int n    = n0 + nrn;

        const float c2 = 0.25f * e2[n];        // REG/(B*T)
        float wv[KDIM];
        #pragma unroll
        for (int k = 0; k < KDIM; k++) wv[k] = w_out[n * KDIM + k];

        // ---- stage z, v (8 n x 300 t) and e1 transposed ----
        for (int idx = tid; idx < 2400; idx += 512) {
            int t = idx >> 3, j = idx & 7;
            int off = (b * TDIM + t) * NDIM + n0 + j;
            s_z[j][t] = z[off];
            s_v[j][t] = v[off];
        }
        if (tid < 32) {                // pad t = 300..303
            int j = tid >> 2, t = 300 + (tid & 3);
            s_z[j][t] = 0.f;
            s_v[j][t] = 0.6f;
        }
        for (int idx = tid; idx < TDIM * KDIM; idx += 512) {
            int t = idx / KDIM, k = idx % KDIM;
            s_et[k][t] = e1[b * TDIM * KDIM + idx];
        }
        if (tid < 40) {                // pad e1T t = 300..303
            int k = tid % KDIM, t = 300 + tid / KDIM;
            s_et[k][t] = 0.f;
        }
        __syncthreads();               // S1

        // ---- per-chunk: post (ballot window) + L (gemv) ----
        float Lr[5], post[5];
        unsigned pm;
        if (half == 0) {
            pm = 0u;
        } else {
            float zp = s_z[nrn][4 * 32 + lane];          // chunk 4 (t 128..159)
            pm = __ballot_sync(0xffffffffu, zp > 0.f);
        }
        #pragma unroll
        for (int cc = 0; cc < 5; cc++) {
            const int t = (half * 5 + cc) * 32 + lane;
            const int ts = (t < 304) ? t : 303;          // safe smem read index
            const float zt = (t < 304) ? s_z[nrn][t] : 0.f;
            const float vt = s_v[nrn][ts];
            const unsigned m = __ballot_sync(0xffffffffu, zt > 0.f);
            const ull w64 = ((ull)m << 32) | (ull)pm;
            const bool refract = ((w64 >> (28 + lane)) & 0xFull) != 0ull;
            pm = m;
            const float vs = (vt - 0.6f) * (1.0f / 0.6f);
            post[cc] = (refract || t >= TDIM)
                     ? 0.f : 0.5f * fmaxf(1.0f - fabsf(vs), 0.0f);
            float Ls = 0.f;
            #pragma unroll
            for (int k = 0; k < KDIM; k++)
                Ls = fmaf(s_et[k][ts], wv[k], Ls);
            Lr[cc] = (t < TDIM) ? Ls : 0.f;
        }

        // ---- Lf = revfilter(L): local rscans + split-half carry ----
        float lf[5], l0[5];
        #pragma unroll
        for (int cc = 0; cc < 5; cc++) {
            lf[cc] = warp_rscan(Lr[cc], lane);
            l0[cc] = __shfl_sync(0xffffffffu, lf[cc], 0);
        }
        if (half == 1) {
            float carry = 0.f;
            #pragma unroll
            for (int cc = 4; cc >= 0; cc--) {
                lf[cc] = fmaf(carry, drl, lf[cc]);
                carry  = fmaf(carry, D32, l0[cc]);
            }
            if (lane == 0) s_c[0][nrn] = carry;          // = Lf(160)
        }
        __syncthreads();               // S2
        if (half == 0) {
            float carry = s_c[0][nrn];
            #pragma unroll
            for (int cc = 4; cc >= 0; cc--) {
                lf[cc] = fmaf(carry, drl, lf[cc]);
                carry  = fmaf(carry, D32, l0[cc]);
            }
        }

        // ---- G2 = post*(Lf + c2); Yr = revfilter(G2) same split scheme ----
        float yr[5];
        #pragma unroll
        for (int cc = 0; cc < 5; cc++) {
            float g2 = post[cc] * (lf[cc] + c2);
            yr[cc] = warp_rscan(g2, lane);
            l0[cc] = __shfl_sync(0xffffffffu, yr[cc], 0);
        }
        if (half == 1) {
            float carry = 0.f;
            #pragma unroll
            for (int cc = 4; cc >= 0; cc--) {
                yr[cc] = fmaf(carry, drl, yr[cc]);
                carry  = fmaf(carry, D32, l0[cc]);
            }
            if (lane == 0) s_c[1][nrn] = carry;          // = Yr(160)
        }
        __syncthreads();               // S3
        if (half == 0) {
            float carry = s_c[1][nrn];
            #pragma unroll
            for (int cc = 4; cc >= 0; cc--) {
                yr[cc] = fmaf(carry, drl, yr[cc]);
                carry  = fmaf(carry, D32, l0[cc]);
            }
        }

        // ---- stage Yr (z tile reuse, guarded t<TDIM) + cooperative store ----
        #pragma unroll
        for (int cc = 0; cc < 5; cc++) {
            int t = (half * 5 + cc) * 32 + lane;
            if (t < TDIM)
                s_z[nrn][t] = yr[cc];
        }
        __syncthreads();               // S4
        for (int idx = tid; idx < 2400; idx += 512) {
            int t = idx >> 3, j = idx & 7;
            g_Yr[(b * TDIM + t) * NDIM + n0 + j] = s_z[j][t];
        }
    } else {
        // ---- e1f = revfilter(e1) for batch b, channels 0..9 (warps 0..9) ----
        const int b = bx - 100;
        float* sE = &s_et[0][0];       // flat [t*10+k], 3040 >= 3000
        for (int i = tid; i < TDIM * KDIM; i += 512)
            sE[i] = e1[b * TDIM * KDIM + i];
        __syncthreads();
        if (wrp < KDIM) {
            float ef[10], l0v[10];
            #pragma unroll
            for (int c = 0; c < 10; c++) {
                int t = c * 32 + lane;
                float xv = (t < TDIM) ? sE[t * KDIM + wrp] : 0.f;
                ef[c] = warp_rscan(xv, lane);
            }
            #pragma unroll
            for (int c = 0; c < 10; c++)
                l0v[c] = __shfl_sync(0xffffffffu, ef[c], 0);
            float carry = 0.f;
            #pragma unroll
            for (int c = 9; c >= 0; c--) {
                float full = fmaf(carry, drl, ef[c]);
                carry = fmaf(carry, D32, l0v[c]);
                int t = c * 32 + lane;
                if (t < TDIM)
                    g_e1f[(b * TDIM + t) * KDIM + wrp] = full;
            }
        }
    }
}

// ---------------------------------------------------------------------------
// Kernel 2: SPARSE spike gather (x, z are exactly {0,1}).
//   dw_in[i,:]  = sum over {bt: x[bt,i]=1}            of Yr[bt,:]
//   dw_rec[i,:] = sum over {bt: z[bt,i]=1, t<299}     of Yr[bt+1,:]
//   dw_out[n,:] = sum over {bt: z[bt,n]=1}            of e1f[bt,:]
//  blocks  0..99  : one x-column i  -> dw_in row i.
//  blocks 100..299: one z-column j  -> dw_rec row j AND dw_out row j (merged:
//                   single column read feeds both).
//  8 warps/block split the 1200 bt rows (150 each); ballot + ffs spike iter;
//  smem 8-way combine; plain STG (no atomics, no zeroing, full coverage).
// ---------------------------------------------------------------------------
__global__ void __launch_bounds__(256) k_sparse(
        const float* __restrict__ x, const float* __restrict__ z,
        float* __restrict__ out) {
    __shared__ float s_acc[8][212];   // [warp][0..199]=main row, [200..209]=dw_out

    const int tid  = threadIdx.x;
    const int lane = tid & 31;
    const int w    = tid >> 5;        // 0..7
    const int bid  = blockIdx.x;

    const bool is_in = (bid < 100);
    const int  j      = is_in ? bid : (bid - 100);
    const int  stride = is_in ? NIN : NDIM;
    const float* src  = is_in ? x : z;

    float4 acc0 = make_float4(0.f, 0.f, 0.f, 0.f);   // cols 4*lane..4*lane+3
    float4 acc1 = make_float4(0.f, 0.f, 0.f, 0.f);   // cols 128+4*lane (lane<18)
    float  accO = 0.f;                               // dw_out col = lane (<10)

    const int bt0 = w * 150;
    #pragma unroll
    for (int c = 0; c < 5; c++) {
        const int off = c * 32 + lane;
        const int bt  = bt0 + off;
        const float sv = (off < 150) ? src[bt * stride + j] : 0.f;
        unsigned mask = __ballot_sync(0xffffffffu, sv > 0.f);
        while (mask) {
            const int p = __ffs(mask) - 1;
            mask &= mask - 1;
            const int sbt = bt0 + c * 32 + p;        // warp-uniform
            if (is_in) {
                const float4* yrow = (const float4*)&g_Yr[sbt * NDIM];
                float4 y0 = yrow[lane];
                acc0.x += y0.x; acc0.y += y0.y; acc0.z += y0.z; acc0.w += y0.w;
                if (lane < 18) {
                    float4 y1 = yrow[32 + lane];
                    acc1.x += y1.x; acc1.y += y1.y; acc1.z += y1.z; acc1.w += y1.w;
                }
            } else {
                // dw_out: e1f row (10 cols)
                if (lane < KDIM) accO += g_e1f[sbt * KDIM + lane];
                // dw_rec: Yr[sbt+1], valid only when t_local < 299
                if ((sbt % TDIM) != TDIM - 1) {
                    const float4* yrow = (const float4*)&g_Yr[(sbt + 1) * NDIM];
                    float4 y0 = yrow[lane];
                    acc0.x += y0.x; acc0.y += y0.y; acc0.z += y0.z; acc0.w += y0.w;
                    if (lane < 18) {
                        float4 y1 = yrow[32 + lane];
                        acc1.x += y1.x; acc1.y += y1.y; acc1.z += y1.z; acc1.w += y1.w;
                    }
                }
            }
        }
    }

    // stash per-warp partials
    float* d = s_acc[w];
    *(float4*)&d[lane * 4] = acc0;                    // cols 0..127
    if (lane < 18) *(float4*)&d[128 + lane * 4] = acc1;  // cols 128..199
    if (lane < KDIM) d[200 + lane] = accO;
    __syncthreads();

    // 8-way combine + store (each out element written by exactly one thread)
    if (tid < NDIM) {
        float s = 0.f;
        #pragma unroll
        for (int ww = 0; ww < 8; ww++) s += s_acc[ww][tid];
        if (is_in) {
            out[j * NDIM + tid] = s;
        } else {
            if (tid == j) s = 0.f;    // autapse mask
            out[NIN * NDIM + j * NDIM + tid] = s;
        }
    } else if (!is_in && tid < NDIM + KDIM) {
        const int k = tid - NDIM;
        float s = 0.f;
        #pragma unroll
        for (int ww = 0; ww < 8; ww++) s += s_acc[ww][200 + k];
        out[NIN * NDIM + NDIM * NDIM + j * KDIM + k] = s;
    }
}

extern "C" void kernel_launch(void* const* d_in, const int* in_sizes, int n_in,
                              void* d_out, int out_size) {
    const float* v     = (const float*)d_in[0];
    const float* z     = (const float*)d_in[1];
    const float* x     = (const float*)d_in[2];
    const float* e1    = (const float*)d_in[3];
    const float* e2    = (const float*)d_in[4];
    const float* w_out = (const float*)d_in[5];
    float* out = (float*)d_out;

    k_g2<<<104, 512>>>(v, z, e1, e2, w_out);
    k_sparse<<<300, 256>>>(x, z, out);
}

// round 16
// speedup vs baseline: 1.1389x; 1.1389x over previous
#include <cuda_runtime.h>

#define BDIM 4
#define TDIM 300
#define NDIM 200
#define NIN  100
#define KDIM 10

#define BTN (BDIM*TDIM*NDIM)     // 240000
#define OUT_TOTAL (NIN*NDIM + NDIM*NDIM + NDIM*KDIM)  // 62000

#define D1  0.8f
#define D2  0.64f
#define D4  0.4096f
#define D8  0.16777216f
#define D16 0.0281474976710656f
#define D32 0.000792281625142643f

// scratch (device globals — no cudaMalloc allowed)
__device__ __align__(16) float g_Yr[BTN];                  // revfilter(G2)
__device__ __align__(16) float g_e1f[BDIM * TDIM * KDIM];  // revfilter(e1)

typedef unsigned long long ull;

__device__ __forceinline__ float dpow_lane(int l) {
    float p = 1.f;
    if (l & 1)  p *= D1;
    if (l & 2)  p *= D2;
    if (l & 4)  p *= D4;
    if (l & 8)  p *= D8;
    if (l & 16) p *= D16;
    return p;
}

__device__ __forceinline__ float warp_rscan(float a, int lane) {
    float tmp;
    tmp = __shfl_down_sync(0xffffffffu, a, 1);  if (lane < 31) a = fmaf(tmp, D1,  a);
    tmp = __shfl_down_sync(0xffffffffu, a, 2);  if (lane < 30) a = fmaf(tmp, D2,  a);
    tmp = __shfl_down_sync(0xffffffffu, a, 4);  if (lane < 28) a = fmaf(tmp, D4,  a);
    tmp = __shfl_down_sync(0xffffffffu, a, 8);  if (lane < 24) a = fmaf(tmp, D8,  a);
    tmp = __shfl_down_sync(0xffffffffu, a, 16); if (lane < 16) a = fmaf(tmp, D16, a);
    return a;
}

// ---------------------------------------------------------------------------
// Kernel 1: G2 + reverse filter -> Yr (split-T, 2 warps per neuron); e1f in
// dedicated blocks. (R15-proven, unchanged.)
// ---------------------------------------------------------------------------
__global__ void __launch_bounds__(512) k_g2(
        const float* __restrict__ v, const float* __restrict__ z,
        const float* __restrict__ e1, const float* __restrict__ e2,
        const float* __restrict__ w_out) {
    __shared__ float s_z[8][304];
    __shared__ float s_v[8][304];
    __shared__ float s_et[10][304];
    __shared__ float s_c[2][8];

    const int tid  = threadIdx.x;
    const int lane = tid & 31;
    const int wrp  = tid >> 5;
    const int bx   = blockIdx.x;

    const float dl  = dpow_lane(lane);
    const float drl = D32 / dl;

    if (bx < 100) {
        const int b  = bx / 25;
        const int n0 = (bx % 25) * 8;
        const int nrn  = wrp >> 1;
        const int half = wrp & 1;
        const int n    = n0 + nrn;

        const float c2 = 0.25f * e2[n];
        float wv[KDIM];
        #pragma unroll
        for (int k = 0; k < KDIM; k++) wv[k] = w_out[n * KDIM + k];

        for (int idx = tid; idx < 2400; idx += 512) {
            int t = idx >> 3, j = idx & 7;
            int off = (b * TDIM + t) * NDIM + n0 + j;
            s_z[j][t] = z[off];
            s_v[j][t] = v[off];
        }
        if (tid < 32) {
            int j = tid >> 2, t = 300 + (tid & 3);
            s_z[j][t] = 0.f;
            s_v[j][t] = 0.6f;
        }
        for (int idx = tid; idx < TDIM * KDIM; idx += 512) {
            int t = idx / KDIM, k = idx % KDIM;
            s_et[k][t] = e1[b * TDIM * KDIM + idx];
        }
        if (tid < 40) {
            int k = tid % KDIM, t = 300 + tid / KDIM;
            s_et[k][t] = 0.f;
        }
        __syncthreads();

        float Lr[5], post[5];
        unsigned pm;
        if (half == 0) {
            pm = 0u;
        } else {
            float zp = s_z[nrn][4 * 32 + lane];
            pm = __ballot_sync(0xffffffffu, zp > 0.f);
        }
        #pragma unroll
        for (int cc = 0; cc < 5; cc++) {
            const int t = (half * 5 + cc) * 32 + lane;
            const int ts = (t < 304) ? t : 303;
            const float zt = (t < 304) ? s_z[nrn][t] : 0.f;
            const float vt = s_v[nrn][ts];
            const unsigned m = __ballot_sync(0xffffffffu, zt > 0.f);
            const ull w64 = ((ull)m << 32) | (ull)pm;
            const bool refract = ((w64 >> (28 + lane)) & 0xFull) != 0ull;
            pm = m;
            const float vs = (vt - 0.6f) * (1.0f / 0.6f);
            post[cc] = (refract || t >= TDIM)
                     ? 0.f : 0.5f * fmaxf(1.0f - fabsf(vs), 0.0f);
            float Ls = 0.f;
            #pragma unroll
            for (int k = 0; k < KDIM; k++)
                Ls = fmaf(s_et[k][ts], wv[k], Ls);
            Lr[cc] = (t < TDIM) ? Ls : 0.f;
        }

        float lf[5], l0[5];
        #pragma unroll
        for (int cc = 0; cc < 5; cc++) {
            lf[cc] = warp_rscan(Lr[cc], lane);
            l0[cc] = __shfl_sync(0xffffffffu, lf[cc], 0);
        }
        if (half == 1) {
            float carry = 0.f;
            #pragma unroll
            for (int cc = 4; cc >= 0; cc--) {
                lf[cc] = fmaf(carry, drl, lf[cc]);
                carry  = fmaf(carry, D32, l0[cc]);
            }
            if (lane == 0) s_c[0][nrn] = carry;
        }
        __syncthreads();
        if (half == 0) {
            float carry = s_c[0][nrn];
            #pragma unroll
            for (int cc = 4; cc >= 0; cc--) {
                lf[cc] = fmaf(carry, drl, lf[cc]);
                carry  = fmaf(carry, D32, l0[cc]);
            }
        }

        float yr[5];
        #pragma unroll
        for (int cc = 0; cc < 5; cc++) {
            float g2 = post[cc] * (lf[cc] + c2);
            yr[cc] = warp_rscan(g2, lane);
            l0[cc] = __shfl_sync(0xffffffffu, yr[cc], 0);
        }
        if (half == 1) {
            float carry = 0.f;
            #pragma unroll
            for (int cc = 4; cc >= 0; cc--) {
                yr[cc] = fmaf(carry, drl, yr[cc]);
                carry  = fmaf(carry, D32, l0[cc]);
            }
            if (lane == 0) s_c[1][nrn] = carry;
        }
        __syncthreads();
        if (half == 0) {
            float carry = s_c[1][nrn];
            #pragma unroll
            for (int cc = 4; cc >= 0; cc--) {
                yr[cc] = fmaf(carry, drl, yr[cc]);
                carry  = fmaf(carry, D32, l0[cc]);
            }
        }

        #pragma unroll
        for (int cc = 0; cc < 5; cc++) {
            int t = (half * 5 + cc) * 32 + lane;
            if (t < TDIM)
                s_z[nrn][t] = yr[cc];
        }
        __syncthreads();
        for (int idx = tid; idx < 2400; idx += 512) {
            int t = idx >> 3, j = idx & 7;
            g_Yr[(b * TDIM + t) * NDIM + n0 + j] = s_z[j][t];
        }
    } else {
        const int b = bx - 100;
        float* sE = &s_et[0][0];
        for (int i = tid; i < TDIM * KDIM; i += 512)
            sE[i] = e1[b * TDIM * KDIM + i];
        __syncthreads();
        if (wrp < KDIM) {
            float ef[10], l0v[10];
            #pragma unroll
            for (int c = 0; c < 10; c++) {
                int t = c * 32 + lane;
                float xv = (t < TDIM) ? sE[t * KDIM + wrp] : 0.f;
                ef[c] = warp_rscan(xv, lane);
            }
            #pragma unroll
            for (int c = 0; c < 10; c++)
                l0v[c] = __shfl_sync(0xffffffffu, ef[c], 0);
            float carry = 0.f;
            #pragma unroll
            for (int c = 9; c >= 0; c--) {
                float full = fmaf(carry, drl, ef[c]);
                carry = fmaf(carry, D32, l0v[c]);
                int t = c * 32 + lane;
                if (t < TDIM)
                    g_e1f[(b * TDIM + t) * KDIM + wrp] = full;
            }
        }
    }
}

// ---------------------------------------------------------------------------
// Kernel 2: SPARSE spike gather v2 — hoisted column loads + dual-stream ILP.
//  blocks  0..99  : x-column i  -> dw_in row i.
//  blocks 100..299: z-column j  -> dw_rec row j + dw_out row j.
//  512 threads = 16 warps; warp w owns bt rows [w*75, w*75+75).
//  All 3 column loads issued together; spikes split into stream A (rows 0..31,
//  32-bit mask) and stream B (rows 32..74, 64-bit mask) with independent
//  accumulators -> 2-4 gather loads in flight. Plain STG epilogue.
// ---------------------------------------------------------------------------
__global__ void __launch_bounds__(512) k_sparse(
        const float* __restrict__ x, const float* __restrict__ z,
        float* __restrict__ out) {
    __shared__ float s_acc[16][212];  // [warp][0..199]=main row, [200..209]=dw_out

    const int tid  = threadIdx.x;
    const int lane = tid & 31;
    const int w    = tid >> 5;        // 0..15
    const int bid  = blockIdx.x;

    const bool is_in = (bid < 100);
    const int  j      = is_in ? bid : (bid - 100);
    const int  stride = is_in ? NIN : NDIM;
    const float* src  = is_in ? x : z;

    const int base = w * 75;          // this warp's bt range [base, base+75)

    // ---- hoisted column loads (3 independent LDGs, one latency) ----
    const float s0 = src[(base + lane) * stride + j];
    const float s1 = src[(base + 32 + lane) * stride + j];
    const float s2 = (lane < 11) ? src[(base + 64 + lane) * stride + j] : 0.f;
    unsigned maskA = __ballot_sync(0xffffffffu, s0 > 0.f);
    const unsigned m1 = __ballot_sync(0xffffffffu, s1 > 0.f);
    const unsigned m2 = __ballot_sync(0xffffffffu, s2 > 0.f);
    ull maskB = (ull)m1 | ((ull)m2 << 32);

    // ---- dual-stream gather ----
    float4 a0A = make_float4(0.f,0.f,0.f,0.f), a1A = make_float4(0.f,0.f,0.f,0.f);
    float4 a0B = make_float4(0.f,0.f,0.f,0.f), a1B = make_float4(0.f,0.f,0.f,0.f);
    float  oA = 0.f, oB = 0.f;

    while (maskA | maskB) {
        int rA = -1, rB = -1;
        if (maskA) {
            int p = __ffs(maskA) - 1;
            maskA &= maskA - 1;
            rA = base + p;
        }
        if (maskB) {
            int p = __ffsll(maskB) - 1;
            maskB &= maskB - 1;
            rB = base + 32 + p;
        }
        if (is_in) {
            if (rA >= 0) {
                const float4* yr = (const float4*)&g_Yr[rA * NDIM];
                float4 y0 = yr[lane];
                a0A.x += y0.x; a0A.y += y0.y; a0A.z += y0.z; a0A.w += y0.w;
                if (lane < 18) {
                    float4 y1 = yr[32 + lane];
                    a1A.x += y1.x; a1A.y += y1.y; a1A.z += y1.z; a1A.w += y1.w;
                }
            }
            if (rB >= 0) {
                const float4* yr = (const float4*)&g_Yr[rB * NDIM];
                float4 y0 = yr[lane];
                a0B.x += y0.x; a0B.y += y0.y; a0B.z += y0.z; a0B.w += y0.w;
                if (lane < 18) {
                    float4 y1 = yr[32 + lane];
                    a1B.x += y1.x; a1B.y += y1.y; a1B.z += y1.z; a1B.w += y1.w;
                }
            }
        } else {
            if (rA >= 0) {
                if (lane < KDIM) oA += g_e1f[rA * KDIM + lane];
                if ((rA % TDIM) != TDIM - 1) {
                    const float4* yr = (const float4*)&g_Yr[(rA + 1) * NDIM];
                    float4 y0 = yr[lane];
                    a0A.x += y0.x; a0A.y += y0.y; a0A.z += y0.z; a0A.w += y0.w;
                    if (lane < 18) {
                        float4 y1 = yr[32 + lane];
                        a1A.x += y1.x; a1A.y += y1.y; a1A.z += y1.z; a1A.w += y1.w;
                    }
                }
            }
            if (rB >= 0) {
                if (lane < KDIM) oB += g_e1f[rB * KDIM + lane];
                if ((rB % TDIM) != TDIM - 1) {
                    const float4* yr = (const float4*)&g_Yr[(rB + 1) * NDIM];
                    float4 y0 = yr[lane];
                    a0B.x += y0.x; a0B.y += y0.y; a0B.z += y0.z; a0B.w += y0.w;
                    if (lane < 18) {
                        float4 y1 = yr[32 + lane];
                        a1B.x += y1.x; a1B.y += y1.y; a1B.z += y1.z; a1B.w += y1.w;
                    }
                }
            }
        }
    }

    // merge streams, stash per-warp partials
    a0A.x += a0B.x; a0A.y += a0B.y; a0A.z += a0B.z; a0A.w += a0B.w;
    a1A.x += a1B.x; a1A.y += a1B.y; a1A.z += a1B.z; a1A.w += a1B.w;
    float* d = s_acc[w];
    *(float4*)&d[lane * 4] = a0A;                        // cols 0..127
    if (lane < 18) *(float4*)&d[128 + lane * 4] = a1A;   // cols 128..199
    if (lane < KDIM) d[200 + lane] = oA + oB;
    __syncthreads();

    // 16-way combine + store (each out element written by exactly one thread)
    if (tid < NDIM) {
        float s = 0.f;
        #pragma unroll
        for (int ww = 0; ww < 16; ww++) s += s_acc[ww][tid];
        if (is_in) {
            out[j * NDIM + tid] = s;
        } else {
            if (tid == j) s = 0.f;    // autapse mask
            out[NIN * NDIM + j * NDIM + tid] = s;
        }
    } else if (!is_in && tid < NDIM + KDIM) {
        const int k = tid - NDIM;
        float s = 0.f;
        #pragma unroll
        for (int ww = 0; ww < 16; ww++) s += s_acc[ww][200 + k];
        out[NIN * NDIM + NDIM * NDIM + j * KDIM + k] = s;
    }
}

extern "C" void kernel_launch(void* const* d_in, const int* in_sizes, int n_in,
                              void* d_out, int out_size) {
    const float* v     = (const float*)d_in[0];
    const float* z     = (const float*)d_in[1];
    const float* x     = (const float*)d_in[2];
    const float* e1    = (const float*)d_in[3];
    const float* e2    = (const float*)d_in[4];
    const float* w_out = (const float*)d_in[5];
    float* out = (float*)d_out;

    k_g2<<<104, 512>>>(v, z, e1, e2, w_out);
    k_sparse<<<300, 512>>>(x, z, out);
}

// round 17
// speedup vs baseline: 1.2262x; 1.0766x over previous
#include <cuda_runtime.h>

#define BDIM 4
#define TDIM 300
#define NDIM 200
#define NIN  100
#define KDIM 10

#define BTN (BDIM*TDIM*NDIM)     // 240000
#define OUT_TOTAL (NIN*NDIM + NDIM*NDIM + NDIM*KDIM)  // 62000

#define D1  0.8f
#define D2  0.64f
#define D4  0.4096f
#define D8  0.16777216f
#define D16 0.0281474976710656f
#define D32 0.000792281625142643f

// scratch (device globals — no cudaMalloc allowed)
__device__ __align__(16) float g_Yr[BTN];                  // revfilter(G2)
__device__ __align__(16) float g_e1f[BDIM * TDIM * KDIM];  // revfilter(e1)

typedef unsigned long long ull;

__device__ __forceinline__ float dpow_lane(int l) {
    float p = 1.f;
    if (l & 1)  p *= D1;
    if (l & 2)  p *= D2;
    if (l & 4)  p *= D4;
    if (l & 8)  p *= D8;
    if (l & 16) p *= D16;
    return p;
}

__device__ __forceinline__ float warp_rscan(float a, int lane) {
    float tmp;
    tmp = __shfl_down_sync(0xffffffffu, a, 1);  if (lane < 31) a = fmaf(tmp, D1,  a);
    tmp = __shfl_down_sync(0xffffffffu, a, 2);  if (lane < 30) a = fmaf(tmp, D2,  a);
    tmp = __shfl_down_sync(0xffffffffu, a, 4);  if (lane < 28) a = fmaf(tmp, D4,  a);
    tmp = __shfl_down_sync(0xffffffffu, a, 8);  if (lane < 24) a = fmaf(tmp, D8,  a);
    tmp = __shfl_down_sync(0xffffffffu, a, 16); if (lane < 16) a = fmaf(tmp, D16, a);
    return a;
}

// ---------------------------------------------------------------------------
// Kernel 1: G2 + reverse filter -> Yr (split-T, 2 warps per neuron); e1f in
// dedicated blocks; zero d_out in dedicated blocks. (R16-proven + zeroing.)
//  blocks  0..99  : (b, 8-neuron tile).
//  blocks 100..103: e1f for batch b = bx-100.
//  blocks 104..105: zero d_out.
// ---------------------------------------------------------------------------
__global__ void __launch_bounds__(512) k_g2(
        const float* __restrict__ v, const float* __restrict__ z,
        const float* __restrict__ e1, const float* __restrict__ e2,
        const float* __restrict__ w_out, float* __restrict__ out) {
    __shared__ float s_z[8][304];
    __shared__ float s_v[8][304];
    __shared__ float s_et[10][304];
    __shared__ float s_c[2][8];

    const int tid  = threadIdx.x;
    const int lane = tid & 31;
    const int wrp  = tid >> 5;
    const int bx   = blockIdx.x;

    const float dl  = dpow_lane(lane);
    const float drl = D32 / dl;

    if (bx < 100) {
        const int b  = bx / 25;
        const int n0 = (bx % 25) * 8;
        const int nrn  = wrp >> 1;
        const int half = wrp & 1;
        const int n    = n0 + nrn;

        const float c2 = 0.25f * e2[n];
        float wv[KDIM];
        #pragma unroll
        for (int k = 0; k < KDIM; k++) wv[k] = w_out[n * KDIM + k];

        for (int idx = tid; idx < 2400; idx += 512) {
            int t = idx >> 3, j = idx & 7;
            int off = (b * TDIM + t) * NDIM + n0 + j;
            s_z[j][t] = z[off];
            s_v[j][t] = v[off];
        }
        if (tid < 32) {
            int j = tid >> 2, t = 300 + (tid & 3);
            s_z[j][t] = 0.f;
            s_v[j][t] = 0.6f;
        }
        for (int idx = tid; idx < TDIM * KDIM; idx += 512) {
            int t = idx / KDIM, k = idx % KDIM;
            s_et[k][t] = e1[b * TDIM * KDIM + idx];
        }
        if (tid < 40) {
            int k = tid % KDIM, t = 300 + tid / KDIM;
            s_et[k][t] = 0.f;
        }
        __syncthreads();

        float Lr[5], post[5];
        unsigned pm;
        if (half == 0) {
            pm = 0u;
        } else {
            float zp = s_z[nrn][4 * 32 + lane];
            pm = __ballot_sync(0xffffffffu, zp > 0.f);
        }
        #pragma unroll
        for (int cc = 0; cc < 5; cc++) {
            const int t = (half * 5 + cc) * 32 + lane;
            const int ts = (t < 304) ? t : 303;
            const float zt = (t < 304) ? s_z[nrn][t] : 0.f;
            const float vt = s_v[nrn][ts];
            const unsigned m = __ballot_sync(0xffffffffu, zt > 0.f);
            const ull w64 = ((ull)m << 32) | (ull)pm;
            const bool refract = ((w64 >> (28 + lane)) & 0xFull) != 0ull;
            pm = m;
            const float vs = (vt - 0.6f) * (1.0f / 0.6f);
            post[cc] = (refract || t >= TDIM)
                     ? 0.f : 0.5f * fmaxf(1.0f - fabsf(vs), 0.0f);
            float Ls = 0.f;
            #pragma unroll
            for (int k = 0; k < KDIM; k++)
                Ls = fmaf(s_et[k][ts], wv[k], Ls);
            Lr[cc] = (t < TDIM) ? Ls : 0.f;
        }

        float lf[5], l0[5];
        #pragma unroll
        for (int cc = 0; cc < 5; cc++) {
            lf[cc] = warp_rscan(Lr[cc], lane);
            l0[cc] = __shfl_sync(0xffffffffu, lf[cc], 0);
        }
        if (half == 1) {
            float carry = 0.f;
            #pragma unroll
            for (int cc = 4; cc >= 0; cc--) {
                lf[cc] = fmaf(carry, drl, lf[cc]);
                carry  = fmaf(carry, D32, l0[cc]);
            }
            if (lane == 0) s_c[0][nrn] = carry;
        }
        __syncthreads();
        if (half == 0) {
            float carry = s_c[0][nrn];
            #pragma unroll
            for (int cc = 4; cc >= 0; cc--) {
                lf[cc] = fmaf(carry, drl, lf[cc]);
                carry  = fmaf(carry, D32, l0[cc]);
            }
        }

        float yr[5];
        #pragma unroll
        for (int cc = 0; cc < 5; cc++) {
            float g2 = post[cc] * (lf[cc] + c2);
            yr[cc] = warp_rscan(g2, lane);
            l0[cc] = __shfl_sync(0xffffffffu, yr[cc], 0);
        }
        if (half == 1) {
            float carry = 0.f;
            #pragma unroll
            for (int cc = 4; cc >= 0; cc--) {
                yr[cc] = fmaf(carry, drl, yr[cc]);
                carry  = fmaf(carry, D32, l0[cc]);
            }
            if (lane == 0) s_c[1][nrn] = carry;
        }
        __syncthreads();
        if (half == 0) {
            float carry = s_c[1][nrn];
            #pragma unroll
            for (int cc = 4; cc >= 0; cc--) {
                yr[cc] = fmaf(carry, drl, yr[cc]);
                carry  = fmaf(carry, D32, l0[cc]);
            }
        }

        #pragma unroll
        for (int cc = 0; cc < 5; cc++) {
            int t = (half * 5 + cc) * 32 + lane;
            if (t < TDIM)
                s_z[nrn][t] = yr[cc];
        }
        __syncthreads();
        for (int idx = tid; idx < 2400; idx += 512) {
            int t = idx >> 3, j = idx & 7;
            g_Yr[(b * TDIM + t) * NDIM + n0 + j] = s_z[j][t];
        }
    } else if (bx < 104) {
        const int b = bx - 100;
        float* sE = &s_et[0][0];
        for (int i = tid; i < TDIM * KDIM; i += 512)
            sE[i] = e1[b * TDIM * KDIM + i];
        __syncthreads();
        if (wrp < KDIM) {
            float ef[10], l0v[10];
            #pragma unroll
            for (int c = 0; c < 10; c++) {
                int t = c * 32 + lane;
                float xv = (t < TDIM) ? sE[t * KDIM + wrp] : 0.f;
                ef[c] = warp_rscan(xv, lane);
            }
            #pragma unroll
            for (int c = 0; c < 10; c++)
                l0v[c] = __shfl_sync(0xffffffffu, ef[c], 0);
            float carry = 0.f;
            #pragma unroll
            for (int c = 9; c >= 0; c--) {
                float full = fmaf(carry, drl, ef[c]);
                carry = fmaf(carry, D32, l0v[c]);
                int t = c * 32 + lane;
                if (t < TDIM)
                    g_e1f[(b * TDIM + t) * KDIM + wrp] = full;
            }
        }
    } else {
        // zero d_out (k_sparse atomically accumulates into it)
        float4 zv = make_float4(0.f, 0.f, 0.f, 0.f);
        for (int i = (bx - 104) * 512 + tid; i < OUT_TOTAL / 4; i += 2 * 512)
            ((float4*)out)[i] = zv;
    }
}

// ---------------------------------------------------------------------------
// Kernel 2: SPARSE spike gather v3 — 4x blocks (split by batch), short chains.
//  grid (300, 4): x = column (0..99 -> dw_in col i; 100..299 -> dw_rec+dw_out
//  col j), y = batch b. 256 threads = 8 warps; warp w owns local-t rows
//  [w*38, w*38+38) of batch b (last warp ragged). Hoisted column loads
//  (1 full + 6-lane tail), dual-stream gather, 8-warp smem combine,
//  atomicAdd into pre-zeroed d_out (4 partials/element).
// ---------------------------------------------------------------------------
__global__ void __launch_bounds__(256) k_sparse(
        const float* __restrict__ x, const float* __restrict__ z,
        float* __restrict__ out) {
    __shared__ float s_acc[8][212];   // [warp][0..199]=main row, [200..209]=dw_out

    const int tid  = threadIdx.x;
    const int lane = tid & 31;
    const int w    = tid >> 5;        // 0..7
    const int col  = blockIdx.x;
    const int b    = blockIdx.y;

    const bool is_in = (col < 100);
    const int  j      = is_in ? col : (col - 100);
    const int  stride = is_in ? NIN : NDIM;
    const float* src  = is_in ? x : z;

    const int tb  = w * 38;           // local t base (last warp: 266..299 valid)
    const int bt0 = b * TDIM;

    // ---- hoisted column loads (2 independent LDGs) ----
    const int tA = tb + lane;
    const int tB = tb + 32 + lane;
    const float sA = (tA < TDIM) ? src[(bt0 + tA) * stride + j] : 0.f;
    const float sB = (lane < 6 && tB < TDIM) ? src[(bt0 + tB) * stride + j] : 0.f;
    unsigned maskA = __ballot_sync(0xffffffffu, sA > 0.f);
    unsigned maskB = __ballot_sync(0xffffffffu, sB > 0.f) & 0x3Fu;

    // ---- dual-stream gather ----
    float4 a0A = make_float4(0.f,0.f,0.f,0.f), a1A = make_float4(0.f,0.f,0.f,0.f);
    float4 a0B = make_float4(0.f,0.f,0.f,0.f), a1B = make_float4(0.f,0.f,0.f,0.f);
    float  oA = 0.f, oB = 0.f;

    while (maskA | maskB) {
        int tLA = -1, tLB = -1;
        if (maskA) {
            int p = __ffs(maskA) - 1;
            maskA &= maskA - 1;
            tLA = tb + p;
        }
        if (maskB) {
            int p = __ffs(maskB) - 1;
            maskB &= maskB - 1;
            tLB = tb + 32 + p;
        }
        if (is_in) {
            if (tLA >= 0) {
                const float4* yr = (const float4*)&g_Yr[(bt0 + tLA) * NDIM];
                float4 y0 = yr[lane];
                a0A.x += y0.x; a0A.y += y0.y; a0A.z += y0.z; a0A.w += y0.w;
                if (lane < 18) {
                    float4 y1 = yr[32 + lane];
                    a1A.x += y1.x; a1A.y += y1.y; a1A.z += y1.z; a1A.w += y1.w;
                }
            }
            if (tLB >= 0) {
                const float4* yr = (const float4*)&g_Yr[(bt0 + tLB) * NDIM];
                float4 y0 = yr[lane];
                a0B.x += y0.x; a0B.y += y0.y; a0B.z += y0.z; a0B.w += y0.w;
                if (lane < 18) {
                    float4 y1 = yr[32 + lane];
                    a1B.x += y1.x; a1B.y += y1.y; a1B.z += y1.z; a1B.w += y1.w;
                }
            }
        } else {
            if (tLA >= 0) {
                if (lane < KDIM) oA += g_e1f[(bt0 + tLA) * KDIM + lane];
                if (tLA < TDIM - 1) {
                    const float4* yr = (const float4*)&g_Yr[(bt0 + tLA + 1) * NDIM];
                    float4 y0 = yr[lane];
                    a0A.x += y0.x; a0A.y += y0.y; a0A.z += y0.z; a0A.w += y0.w;
                    if (lane < 18) {
                        float4 y1 = yr[32 + lane];
                        a1A.x += y1.x; a1A.y += y1.y; a1A.z += y1.z; a1A.w += y1.w;
                    }
                }
            }
            if (tLB >= 0) {
                if (lane < KDIM) oB += g_e1f[(bt0 + tLB) * KDIM + lane];
                if (tLB < TDIM - 1) {
                    const float4* yr = (const float4*)&g_Yr[(bt0 + tLB + 1) * NDIM];
                    float4 y0 = yr[lane];
                    a0B.x += y0.x; a0B.y += y0.y; a0B.z += y0.z; a0B.w += y0.w;
                    if (lane < 18) {
                        float4 y1 = yr[32 + lane];
                        a1B.x += y1.x; a1B.y += y1.y; a1B.z += y1.z; a1B.w += y1.w;
                    }
                }
            }
        }
    }

    // merge streams, stash per-warp partials
    a0A.x += a0B.x; a0A.y += a0B.y; a0A.z += a0B.z; a0A.w += a0B.w;
    a1A.x += a1B.x; a1A.y += a1B.y; a1A.z += a1B.z; a1A.w += a1B.w;
    float* d = s_acc[w];
    *(float4*)&d[lane * 4] = a0A;                        // cols 0..127
    if (lane < 18) *(float4*)&d[128 + lane * 4] = a1A;   // cols 128..199
    if (lane < KDIM) d[200 + lane] = oA + oB;
    __syncthreads();

    // 8-way combine + atomicAdd (4 b-partials per output element)
    if (tid < NDIM) {
        float s = 0.f;
        #pragma unroll
        for (int ww = 0; ww < 8; ww++) s += s_acc[ww][tid];
        if (is_in) {
            atomicAdd(&out[j * NDIM + tid], s);
        } else if (tid != j) {        // autapse: diagonal never added
            atomicAdd(&out[NIN * NDIM + j * NDIM + tid], s);
        }
    } else if (!is_in && tid < NDIM + KDIM) {
        const int k = tid - NDIM;
        float s = 0.f;
        #pragma unroll
        for (int ww = 0; ww < 8; ww++) s += s_acc[ww][200 + k];
        atomicAdd(&out[NIN * NDIM + NDIM * NDIM + j * KDIM + k], s);
    }
}

extern "C" void kernel_launch(void* const* d_in, const int* in_sizes, int n_in,
                              void* d_out, int out_size) {
    const float* v     = (const float*)d_in[0];
    const float* z     = (const float*)d_in[1];
    const float* x     = (const float*)d_in[2];
    const float* e1    = (const float*)d_in[3];
    const float* e2    = (const float*)d_in[4];
    const float* w_out = (const float*)d_in[5];
    float* out = (float*)d_out;

    k_g2<<<106, 512>>>(v, z, e1, e2, w_out, out);
    k_sparse<<<dim3(300, 4), 256>>>(x, z, out);
}